// round 12
// baseline (speedup 1.0000x reference)
#include <cuda_runtime.h>
#include <cuda_fp16.h>
#include <cstdint>
#include <cstddef>

// Problem dims (fixed by the reference)
#define NN     20000
#define EE     320000
#define INC    2000
#define HIDDEN 512
#define OUTD   256
#define QD     100
#define QPAD   128     // x_ADT K padded to 128 for 16B-aligned fp16 rows

// ---------------------------------------------------------------------------
// Scratch (device globals; no dynamic allocation allowed)
// ---------------------------------------------------------------------------
__device__ __align__(16) __half g_ah  [NN * INC];      // fp16 x_RNA (80MB)
__device__ __align__(16) __half g_adth[NN * QPAD];     // fp16 x_ADT padded
__device__ __align__(16) __half g_xsh [NN * HIDDEN];   // fp16 xs / fusion A1
__device__ __align__(16) __half g_xdh [NN * HIDDEN];   // fp16 xd / fusion A2
__device__ __align__(16) __half g_wth [2605056];       // fp16 transposed weights [N][K]
__device__ float g_h  [NN * HIDDEN];   // GEMM outputs (pre-aggregation, fp32)
__device__ float g_xs [NN * HIDDEN];   // agg outputs layer 1 (fp32)
__device__ float g_xd [NN * HIDDEN];
__device__ float g_dinv[3 * NN];       // deg^-0.5 for sim / dist / common

// weight segment offsets in g_wth (halves; all multiples of 8 -> 16B aligned)
#define WT_RNA1 0
#define WT_RNA2 1024000
#define WT_SIM  2048000
#define WT_DIST 2179072
#define WT_P3   2310144
#define WT_F1   2342912
#define WT_F2   2473984

// ---------------------------------------------------------------------------
// PTX helpers
// ---------------------------------------------------------------------------
__device__ __forceinline__ uint32_t smem_u32(const void* p) {
    uint32_t a;
    asm("{ .reg .u64 t; cvta.to.shared.u64 t, %1; cvt.u32.u64 %0, t; }" : "=r"(a) : "l"(p));
    return a;
}
__device__ __forceinline__ void cp_async16(uint32_t sa, const void* g, int src_size) {
    asm volatile("cp.async.cg.shared.global [%0], [%1], 16, %2;"
                 :: "r"(sa), "l"(g), "r"(src_size));
}
#define LDSM_X4(r0, r1, r2, r3, addr) \
    asm volatile("ldmatrix.sync.aligned.m8n8.x4.shared.b16 {%0,%1,%2,%3}, [%4];" \
                 : "=r"(r0), "=r"(r1), "=r"(r2), "=r"(r3) : "r"(addr))

// ---------------------------------------------------------------------------
// Small utility kernels
// ---------------------------------------------------------------------------
__global__ void fill_ones(float* __restrict__ p, int n) {
    int i = blockIdx.x * blockDim.x + threadIdx.x;
    if (i < n) p[i] = 1.0f;
}

__global__ void deg_accum(const int* __restrict__ dst, const float* __restrict__ w,
                          float* __restrict__ deg, int E) {
    int e = blockIdx.x * blockDim.x + threadIdx.x;
    if (e < E) atomicAdd(&deg[dst[e]], w[e]);
}

__global__ void rsqrt_inplace(float* __restrict__ p, int n) {
    int i = blockIdx.x * blockDim.x + threadIdx.x;
    if (i < n) p[i] = rsqrtf(p[i]);   // deg >= 1 always (self-loop weight 1)
}

// fp32 -> fp16 copy (prepare GEMM A operands); n4 = element count / 4
__global__ void cvt_fp16(const float* __restrict__ in, __half* __restrict__ out, int n4) {
    int i = blockIdx.x * blockDim.x + threadIdx.x;
    if (i >= n4) return;
    float4 v = reinterpret_cast<const float4*>(in)[i];
    reinterpret_cast<__half2*>(out)[2 * i]     = __floats2half2_rn(v.x, v.y);
    reinterpret_cast<__half2*>(out)[2 * i + 1] = __floats2half2_rn(v.z, v.w);
}

// relu(x) -> fp16 (layer-1 activations feeding layer-2 GEMMs)
__global__ void relu_cvt(const float* __restrict__ in, __half* __restrict__ out, int n4) {
    int i = blockIdx.x * blockDim.x + threadIdx.x;
    if (i >= n4) return;
    float4 v = reinterpret_cast<const float4*>(in)[i];
    v.x = fmaxf(v.x, 0.f); v.y = fmaxf(v.y, 0.f);
    v.z = fmaxf(v.z, 0.f); v.w = fmaxf(v.w, 0.f);
    reinterpret_cast<__half2*>(out)[2 * i]     = __floats2half2_rn(v.x, v.y);
    reinterpret_cast<__half2*>(out)[2 * i + 1] = __floats2half2_rn(v.z, v.w);
}

// x_ADT [NN][100] fp32 -> [NN][128] fp16 zero-padded
__global__ void pad_adt(const float* __restrict__ in, __half* __restrict__ out) {
    int idx = blockIdx.x * blockDim.x + threadIdx.x;
    if (idx >= NN * QPAD) return;
    int r = idx >> 7, k = idx & (QPAD - 1);
    out[idx] = (k < QD) ? __float2half(in[r * QD + k]) : __half(0.f);
}

// in fp32 [R][C] -> out fp16 [C][RP], zero-padded rows beyond R
__global__ void transpose_cvt(const float* __restrict__ in, __half* __restrict__ out,
                              int R, int C, int RP) {
    __shared__ float t[32][33];
    int c0 = blockIdx.x * 32, r0 = blockIdx.y * 32;
    for (int dy = threadIdx.y; dy < 32; dy += 8) {
        int r = r0 + dy, c = c0 + threadIdx.x;
        t[dy][threadIdx.x] = (r < R && c < C) ? in[(size_t)r * C + c] : 0.f;
    }
    __syncthreads();
    for (int dy = threadIdx.y; dy < 32; dy += 8) {
        int oc = c0 + dy, orw = r0 + threadIdx.x;
        if (oc < C && orw < RP) out[(size_t)oc * RP + orw] = __float2half(t[threadIdx.x][dy]);
    }
}

// agg[i,f] = h[i,f] * dinv[i]^2 + bias[f]   (self-loop term + bias, overwrites dst)
__global__ void agg_init(const float* __restrict__ h, const float* __restrict__ dinv,
                         const float* __restrict__ bias, float* __restrict__ agg, int F) {
    int idx4 = blockIdx.x * blockDim.x + threadIdx.x;
    int fdiv4 = F >> 2;
    int total4 = NN * fdiv4;
    if (idx4 >= total4) return;
    int node = idx4 / fdiv4;
    int f4   = idx4 - node * fdiv4;
    float di = dinv[node];
    float s  = di * di;
    float4 hv = reinterpret_cast<const float4*>(h)[idx4];
    float4 bv = *reinterpret_cast<const float4*>(bias + (f4 << 2));
    float4 o;
    o.x = hv.x * s + bv.x;
    o.y = hv.y * s + bv.y;
    o.z = hv.z * s + bv.z;
    o.w = hv.w * s + bv.w;
    reinterpret_cast<float4*>(agg)[idx4] = o;
}

// Scatter-add: agg[dst] += h[src] * (dinv[src]*w*dinv[dst]) using vector reductions.
__global__ void edge_agg(const float* __restrict__ h, float* __restrict__ agg,
                         const int* __restrict__ src, const int* __restrict__ dst,
                         const float* __restrict__ ew, const float* __restrict__ dinv,
                         int E, int F) {
    int lanes = F >> 2;                       // float4 lanes per edge (128 or 64)
    int epb   = blockDim.x / lanes;           // edges per block
    int le    = threadIdx.x / lanes;
    int lane  = threadIdx.x - le * lanes;
    int e     = blockIdx.x * epb + le;
    if (e >= E) return;

    int s = src[e];
    int d = dst[e];
    float norm = dinv[s] * ew[e] * dinv[d];

    float4 hv = *reinterpret_cast<const float4*>(h + (size_t)s * F + (lane << 2));
    float* outp = agg + (size_t)d * F + (lane << 2);
    asm volatile("red.global.add.v4.f32 [%0], {%1, %2, %3, %4};"
                 :: "l"(outp),
                    "f"(hv.x * norm), "f"(hv.y * norm),
                    "f"(hv.z * norm), "f"(hv.w * norm)
                 : "memory");
}

// ---------------------------------------------------------------------------
// fp16 tensor-core GEMM: C[M,Ntot](fp32) = concat(A1,A2)[M,K](fp16) @ BT^T (+bias)
// BT fp16 [Ntot][K] (K-major). BM=BN=128, BK=64, 8 warps (2m x 4n), warp 64x32,
// mma m16n8k16.f16.f32. Smem: XOR-swizzled 128B rows (conflict-free ldmatrix),
// 2-stage cp.async. Requires: K % 8 == 0, K1 % 8 == 0, Ntot % 128 == 0,
// 16B-aligned rows (all call sites satisfy).
// ---------------------------------------------------------------------------
__global__ void __launch_bounds__(256, 2)
hgemm(const __half* __restrict__ A1, const __half* __restrict__ A2, int K1,
      const __half* __restrict__ BT, const float* __restrict__ bias,
      float* __restrict__ C, int M, int Ntot, int K)
{
    extern __shared__ __align__(128) char smem[];
    const uint32_t sb = smem_u32(smem);

    const int tid  = threadIdx.x;
    const int lane = tid & 31;
    const int warp = tid >> 5;
    const int wm   = warp >> 2;     // 0..1
    const int wn   = warp & 3;      // 0..3
    const int block_row = blockIdx.y * 128;
    const int block_col = blockIdx.x * 128;

    float acc[4][4][4];
    #pragma unroll
    for (int mt = 0; mt < 4; mt++)
        #pragma unroll
        for (int nt = 0; nt < 4; nt++)
            #pragma unroll
            for (int q = 0; q < 4; q++) acc[mt][nt][q] = 0.0f;

    // ldmatrix lane geometry
    const int lr = lane & 7;            // row within 8x8 matrix
    const int lm = (lane >> 3) & 1;     // +8 rows for matrices 1,3
    const int lc = lane >> 4;           // +1 chunk (8 halves) for matrices 2,3
    uint32_t a_off[4], a_x[4];
    #pragma unroll
    for (int mt = 0; mt < 4; mt++) {
        int row = wm * 64 + mt * 16 + lm * 8 + lr;
        a_off[mt] = (uint32_t)row * 128u;
        a_x[mt]   = (uint32_t)(row & 7);
    }
    uint32_t b_off[2], b_x[2];
    #pragma unroll
    for (int p = 0; p < 2; p++) {
        int row = wn * 32 + p * 16 + lm * 8 + lr;
        b_off[p] = (uint32_t)row * 128u;
        b_x[p]   = (uint32_t)(row & 7);
    }

    const int T = (K + 63) >> 6;

    auto load_tile = [&](int it) {
        int s = it & 1;
        uint32_t ab = sb + (uint32_t)s * 32768u;
        uint32_t bb = ab + 16384u;
        int k0 = it * 64;
        #pragma unroll
        for (int i = 0; i < 4; i++) {         // A: 128 rows x 8 chunks of 16B
            int id = tid + i * 256;
            int r = id >> 3, c = id & 7;
            int gm = block_row + r;
            int ge = k0 + c * 8;              // in halves
            const void* src = (const void*)A1;
            int sz = 0;
            if (gm < M && ge < K) {
                src = (ge < K1) ? (const void*)(A1 + (size_t)gm * K1 + ge)
                                : (const void*)(A2 + (size_t)gm * (K - K1) + (ge - K1));
                sz = 16;
            }
            cp_async16(ab + (uint32_t)(r * 128) + (uint32_t)(((c ^ (r & 7)) << 4)), src, sz);
        }
        #pragma unroll
        for (int i = 0; i < 4; i++) {         // B: 128 rows x 8 chunks of 16B
            int id = tid + i * 256;
            int n = id >> 3, c = id & 7;
            int ge = k0 + c * 8;
            const void* src = (const void*)BT;
            int sz = 0;
            if (ge < K) {
                src = (const void*)(BT + (size_t)(block_col + n) * K + ge);
                sz = 16;
            }
            cp_async16(bb + (uint32_t)(n * 128) + (uint32_t)(((c ^ (n & 7)) << 4)), src, sz);
        }
        asm volatile("cp.async.commit_group;" ::: "memory");
    };

    load_tile(0);
    if (T > 1) load_tile(1);

    for (int it = 0; it < T; it++) {
        if (it + 1 < T) asm volatile("cp.async.wait_group 1;" ::: "memory");
        else            asm volatile("cp.async.wait_group 0;" ::: "memory");
        __syncthreads();

        uint32_t ab = sb + (uint32_t)(it & 1) * 32768u;
        uint32_t bb = ab + 16384u;

        #pragma unroll
        for (int ks = 0; ks < 4; ks++) {
            unsigned a[4][4];
            #pragma unroll
            for (int mt = 0; mt < 4; mt++) {
                uint32_t ch = (uint32_t)(2 * ks) + (uint32_t)lc;
                LDSM_X4(a[mt][0], a[mt][1], a[mt][2], a[mt][3],
                        ab + a_off[mt] + ((ch ^ a_x[mt]) << 4));
            }
            unsigned b0[4], b1[4];
            #pragma unroll
            for (int p = 0; p < 2; p++) {
                uint32_t ch = (uint32_t)(2 * ks) + (uint32_t)lc;
                unsigned r0, r1, r2, r3;
                LDSM_X4(r0, r1, r2, r3, bb + b_off[p] + ((ch ^ b_x[p]) << 4));
                b0[2 * p] = r0; b0[2 * p + 1] = r1;
                b1[2 * p] = r2; b1[2 * p + 1] = r3;
            }
            #pragma unroll
            for (int mt = 0; mt < 4; mt++)
                #pragma unroll
                for (int nt = 0; nt < 4; nt++) {
                    asm volatile(
                        "mma.sync.aligned.m16n8k16.row.col.f32.f16.f16.f32 "
                        "{%0,%1,%2,%3}, {%4,%5,%6,%7}, {%8,%9}, {%0,%1,%2,%3};"
                        : "+f"(acc[mt][nt][0]), "+f"(acc[mt][nt][1]),
                          "+f"(acc[mt][nt][2]), "+f"(acc[mt][nt][3])
                        : "r"(a[mt][0]), "r"(a[mt][1]), "r"(a[mt][2]), "r"(a[mt][3]),
                          "r"(b0[nt]), "r"(b1[nt]));
                }
        }
        __syncthreads();
        if (it + 2 < T) load_tile(it + 2);
    }

    // ---- epilogue ----
    #pragma unroll
    for (int mt = 0; mt < 4; mt++) {
        int r0 = block_row + wm * 64 + mt * 16 + (lane >> 2);
        #pragma unroll
        for (int nt = 0; nt < 4; nt++) {
            int c = block_col + wn * 32 + nt * 8 + 2 * (lane & 3);
            if (r0 < M) {
                float2 v = make_float2(acc[mt][nt][0], acc[mt][nt][1]);
                if (bias) { v.x += bias[c]; v.y += bias[c + 1]; }
                *reinterpret_cast<float2*>(C + (size_t)r0 * Ntot + c) = v;
            }
            int r1 = r0 + 8;
            if (r1 < M) {
                float2 v = make_float2(acc[mt][nt][2], acc[mt][nt][3]);
                if (bias) { v.x += bias[c]; v.y += bias[c + 1]; }
                *reinterpret_cast<float2*>(C + (size_t)r1 * Ntot + c) = v;
            }
        }
    }
}

#define HGEMM_SMEM 65536

static void gemm_h(const __half* A1, const __half* A2, int K1,
                   const __half* BT, const float* bias, float* C,
                   int M, int Ntot, int K) {
    dim3 grid(Ntot / 128, (M + 127) / 128);
    hgemm<<<grid, 256, HGEMM_SMEM>>>(A1, A2, K1, BT, bias, C, M, Ntot, K);
}

// ---------------------------------------------------------------------------
// Launch orchestration
// ---------------------------------------------------------------------------
extern "C" void kernel_launch(void* const* d_in, const int* in_sizes, int n_in,
                              void* d_out, int out_size) {
    const float* x_RNA     = (const float*)d_in[0];
    const float* x_ADT     = (const float*)d_in[1];
    const int*   sim_ei    = (const int*)  d_in[2];   // [2,E]: row0=src, row1=dst
    const float* sim_ew    = (const float*)d_in[3];
    const int*   dist_ei   = (const int*)  d_in[4];
    const float* dist_ew   = (const float*)d_in[5];
    const int*   common_ei = (const int*)  d_in[6];
    const float* common_ew = (const float*)d_in[7];
    const float* W_rna1    = (const float*)d_in[8];
    const float* b_rna1    = (const float*)d_in[9];
    const float* W_rna2    = (const float*)d_in[10];
    const float* b_rna2    = (const float*)d_in[11];
    const float* W_p3      = (const float*)d_in[12];
    const float* b_p3      = (const float*)d_in[13];
    const float* W_sim     = (const float*)d_in[14];
    const float* b_sim     = (const float*)d_in[15];
    const float* W_dist    = (const float*)d_in[16];
    const float* b_dist    = (const float*)d_in[17];
    const float* W_f1      = (const float*)d_in[18];
    const float* b_f1      = (const float*)d_in[19];
    const float* W_f2      = (const float*)d_in[20];
    const float* b_f2      = (const float*)d_in[21];

    float* out = (float*)d_out;
    const size_t SEC = (size_t)NN * OUTD;
    float* out_xsim  = out;
    float* out_xdist = out + SEC;
    float* out_fused = out + 2 * SEC;
    float* out_fpro  = out + 3 * SEC;
    float* out_pro   = out + 4 * SEC;

    __half *ah, *adth, *xsh, *xdh, *wt;
    float  *h, *xs, *xd, *dinv;
    cudaGetSymbolAddress((void**)&ah,   g_ah);
    cudaGetSymbolAddress((void**)&adth, g_adth);
    cudaGetSymbolAddress((void**)&xsh,  g_xsh);
    cudaGetSymbolAddress((void**)&xdh,  g_xdh);
    cudaGetSymbolAddress((void**)&wt,   g_wth);
    cudaGetSymbolAddress((void**)&h,    g_h);
    cudaGetSymbolAddress((void**)&xs,   g_xs);
    cudaGetSymbolAddress((void**)&xd,   g_xd);
    cudaGetSymbolAddress((void**)&dinv, g_dinv);
    float* dinv_sim    = dinv;
    float* dinv_dist   = dinv + NN;
    float* dinv_common = dinv + 2 * NN;

    cudaFuncSetAttribute(hgemm, cudaFuncAttributeMaxDynamicSharedMemorySize, HGEMM_SMEM);

    // ---- degree normalization for all three graphs ----
    fill_ones<<<(3 * NN + 255) / 256, 256>>>(dinv, 3 * NN);
    deg_accum<<<(EE + 255) / 256, 256>>>(sim_ei + EE,    sim_ew,    dinv_sim,    EE);
    deg_accum<<<(EE + 255) / 256, 256>>>(dist_ei + EE,   dist_ew,   dinv_dist,   EE);
    deg_accum<<<(EE + 255) / 256, 256>>>(common_ei + EE, common_ew, dinv_common, EE);
    rsqrt_inplace<<<(3 * NN + 255) / 256, 256>>>(dinv, 3 * NN);

    // ---- operand conversion: weights (transpose to [N][K] fp16) + A matrices ----
    dim3 tb(32, 8);
    transpose_cvt<<<dim3((HIDDEN + 31) / 32, (INC  + 31) / 32), tb>>>(W_rna1, wt + WT_RNA1, INC,    HIDDEN, INC);
    transpose_cvt<<<dim3((HIDDEN + 31) / 32, (INC  + 31) / 32), tb>>>(W_rna2, wt + WT_RNA2, INC,    HIDDEN, INC);
    transpose_cvt<<<dim3((OUTD + 31) / 32, (HIDDEN + 31) / 32), tb>>>(W_sim,  wt + WT_SIM,  HIDDEN, OUTD,   HIDDEN);
    transpose_cvt<<<dim3((OUTD + 31) / 32, (HIDDEN + 31) / 32), tb>>>(W_dist, wt + WT_DIST, HIDDEN, OUTD,   HIDDEN);
    transpose_cvt<<<dim3((OUTD + 31) / 32, (QPAD   + 31) / 32), tb>>>(W_p3,   wt + WT_P3,   QD,     OUTD,   QPAD);
    transpose_cvt<<<dim3((OUTD + 31) / 32, (2*OUTD + 31) / 32), tb>>>(W_f1,   wt + WT_F1,   2*OUTD, OUTD,   2*OUTD);
    transpose_cvt<<<dim3((OUTD + 31) / 32, (2*OUTD + 31) / 32), tb>>>(W_f2,   wt + WT_F2,   2*OUTD, OUTD,   2*OUTD);

    cvt_fp16<<<(NN * INC / 4 + 255) / 256, 256>>>(x_RNA, ah, NN * INC / 4);
    pad_adt<<<(NN * QPAD + 255) / 256, 256>>>(x_ADT, adth);

    const int grid512 = (NN * (HIDDEN / 4) + 255) / 256;
    const int grid256 = (NN * (OUTD / 4) + 255) / 256;
    const int egrid512 = (EE + 1) / 2;   // 2 edges/block @ F=512, 256 threads
    const int egrid256 = (EE + 3) / 4;   // 4 edges/block @ F=256
    const int c512 = (NN * HIDDEN / 4 + 255) / 256;
    const int c256 = (NN * OUTD / 4 + 255) / 256;

    // ---- pro = gcn(x_ADT, common; W_p3, b_p3) -> d_out[4] ----
    gemm_h(adth, adth, QPAD, wt + WT_P3, nullptr, h, NN, OUTD, QPAD);
    agg_init<<<grid256, 256>>>(h, dinv_common, b_p3, out_pro, OUTD);
    edge_agg<<<egrid256, 256>>>(h, out_pro, common_ei, common_ei + EE, common_ew, dinv_common, EE, OUTD);

    // ---- Layer 1, sim: xs = relu(gcn(x_RNA, sim; W_rna1, b_rna1)) ----
    gemm_h(ah, ah, INC, wt + WT_RNA1, nullptr, h, NN, HIDDEN, INC);
    agg_init<<<grid512, 256>>>(h, dinv_sim, b_rna1, xs, HIDDEN);
    edge_agg<<<egrid512, 256>>>(h, xs, sim_ei, sim_ei + EE, sim_ew, dinv_sim, EE, HIDDEN);
    relu_cvt<<<c512, 256>>>(xs, xsh, NN * HIDDEN / 4);

    // ---- Layer 1, dist: xd = relu(gcn(x_RNA, dist; W_rna2, b_rna2)) ----
    gemm_h(ah, ah, INC, wt + WT_RNA2, nullptr, h, NN, HIDDEN, INC);
    agg_init<<<grid512, 256>>>(h, dinv_dist, b_rna2, xd, HIDDEN);
    edge_agg<<<egrid512, 256>>>(h, xd, dist_ei, dist_ei + EE, dist_ew, dinv_dist, EE, HIDDEN);
    relu_cvt<<<c512, 256>>>(xd, xdh, NN * HIDDEN / 4);

    // ---- Layer 2: x_sim = gcn(xs, sim; W_sim, b_sim) -> d_out[0] ----
    gemm_h(xsh, xsh, HIDDEN, wt + WT_SIM, nullptr, h, NN, OUTD, HIDDEN);
    agg_init<<<grid256, 256>>>(h, dinv_sim, b_sim, out_xsim, OUTD);
    edge_agg<<<egrid256, 256>>>(h, out_xsim, sim_ei, sim_ei + EE, sim_ew, dinv_sim, EE, OUTD);

    // ---- Layer 2: x_dist = gcn(xd, dist; W_dist, b_dist) -> d_out[1] ----
    gemm_h(xdh, xdh, HIDDEN, wt + WT_DIST, nullptr, h, NN, OUTD, HIDDEN);
    agg_init<<<grid256, 256>>>(h, dinv_dist, b_dist, out_xdist, OUTD);
    edge_agg<<<egrid256, 256>>>(h, out_xdist, dist_ei, dist_ei + EE, dist_ew, dinv_dist, EE, OUTD);

    // ---- fused = concat(x_sim, x_dist) @ W_f1 + b_f1 -> d_out[2] (K-split) ----
    cvt_fp16<<<c256, 256>>>(out_xsim,  xsh, NN * OUTD / 4);
    cvt_fp16<<<c256, 256>>>(out_xdist, xdh, NN * OUTD / 4);
    gemm_h(xsh, xdh, OUTD, wt + WT_F1, b_f1, out_fused, NN, OUTD, 2 * OUTD);

    // ---- fused_pro = concat(fused, pro) @ W_f2 + b_f2 -> d_out[3] ----
    cvt_fp16<<<c256, 256>>>(out_fused, xsh, NN * OUTD / 4);
    cvt_fp16<<<c256, 256>>>(out_pro,   xdh, NN * OUTD / 4);
    gemm_h(xsh, xdh, OUTD, wt + WT_F2, b_f2, out_fpro, NN, OUTD, 2 * OUTD);
}

// round 13
// speedup vs baseline: 1.0002x; 1.0002x over previous
#include <cuda_runtime.h>
#include <cuda_fp16.h>
#include <cstdint>
#include <cstddef>

// Problem dims (fixed by the reference)
#define NN     20000
#define EE     320000
#define INC    2000
#define HIDDEN 512
#define OUTD   256
#define QD     100
#define QPAD   128     // x_ADT K padded to 128 for 16B-aligned fp16 rows

// ---------------------------------------------------------------------------
// Scratch (device globals; no dynamic allocation allowed)
// ---------------------------------------------------------------------------
__device__ __align__(16) __half g_ah  [NN * INC];      // fp16 x_RNA (80MB)
__device__ __align__(16) __half g_adth[NN * QPAD];     // fp16 x_ADT padded
__device__ __align__(16) __half g_xsh [NN * HIDDEN];   // fp16 xs / fusion A1
__device__ __align__(16) __half g_xdh [NN * HIDDEN];   // fp16 xd / fusion A2
__device__ __align__(16) __half g_wth [2605056];       // fp16 transposed weights [N][K]
__device__ float g_h  [NN * HIDDEN];   // GEMM outputs (pre-aggregation, fp32)
__device__ float g_xs [NN * HIDDEN];   // agg outputs layer 1 (fp32)
__device__ float g_xd [NN * HIDDEN];
__device__ float g_dinv[3 * NN];       // deg^-0.5 for sim / dist / common

// weight segment offsets in g_wth (halves; all multiples of 8 -> 16B aligned)
#define WT_RNA1 0
#define WT_RNA2 1024000
#define WT_SIM  2048000
#define WT_DIST 2179072
#define WT_P3   2310144
#define WT_F1   2342912
#define WT_F2   2473984

// ---------------------------------------------------------------------------
// PTX helpers
// ---------------------------------------------------------------------------
__device__ __forceinline__ uint32_t smem_u32(const void* p) {
    uint32_t a;
    asm("{ .reg .u64 t; cvta.to.shared.u64 t, %1; cvt.u32.u64 %0, t; }" : "=r"(a) : "l"(p));
    return a;
}
__device__ __forceinline__ void cp_async16(uint32_t sa, const void* g, int src_size) {
    asm volatile("cp.async.cg.shared.global [%0], [%1], 16, %2;"
                 :: "r"(sa), "l"(g), "r"(src_size));
}
#define LDSM_X4(r0, r1, r2, r3, addr) \
    asm volatile("ldmatrix.sync.aligned.m8n8.x4.shared.b16 {%0,%1,%2,%3}, [%4];" \
                 : "=r"(r0), "=r"(r1), "=r"(r2), "=r"(r3) : "r"(addr))

// ---------------------------------------------------------------------------
// Small utility kernels
// ---------------------------------------------------------------------------
__global__ void fill_ones(float* __restrict__ p, int n) {
    int i = blockIdx.x * blockDim.x + threadIdx.x;
    if (i < n) p[i] = 1.0f;
}

__global__ void deg_accum(const int* __restrict__ dst, const float* __restrict__ w,
                          float* __restrict__ deg, int E) {
    int e = blockIdx.x * blockDim.x + threadIdx.x;
    if (e < E) atomicAdd(&deg[dst[e]], w[e]);
}

__global__ void rsqrt_inplace(float* __restrict__ p, int n) {
    int i = blockIdx.x * blockDim.x + threadIdx.x;
    if (i < n) p[i] = rsqrtf(p[i]);   // deg >= 1 always (self-loop weight 1)
}

// fp32 -> fp16 copy (prepare GEMM A operands); n4 = element count / 4
__global__ void cvt_fp16(const float* __restrict__ in, __half* __restrict__ out, int n4) {
    int i = blockIdx.x * blockDim.x + threadIdx.x;
    if (i >= n4) return;
    float4 v = reinterpret_cast<const float4*>(in)[i];
    reinterpret_cast<__half2*>(out)[2 * i]     = __floats2half2_rn(v.x, v.y);
    reinterpret_cast<__half2*>(out)[2 * i + 1] = __floats2half2_rn(v.z, v.w);
}

// relu(x) -> fp16 (layer-1 activations feeding layer-2 GEMMs)
__global__ void relu_cvt(const float* __restrict__ in, __half* __restrict__ out, int n4) {
    int i = blockIdx.x * blockDim.x + threadIdx.x;
    if (i >= n4) return;
    float4 v = reinterpret_cast<const float4*>(in)[i];
    v.x = fmaxf(v.x, 0.f); v.y = fmaxf(v.y, 0.f);
    v.z = fmaxf(v.z, 0.f); v.w = fmaxf(v.w, 0.f);
    reinterpret_cast<__half2*>(out)[2 * i]     = __floats2half2_rn(v.x, v.y);
    reinterpret_cast<__half2*>(out)[2 * i + 1] = __floats2half2_rn(v.z, v.w);
}

// x_ADT [NN][100] fp32 -> [NN][128] fp16 zero-padded
__global__ void pad_adt(const float* __restrict__ in, __half* __restrict__ out) {
    int idx = blockIdx.x * blockDim.x + threadIdx.x;
    if (idx >= NN * QPAD) return;
    int r = idx >> 7, k = idx & (QPAD - 1);
    out[idx] = (k < QD) ? __float2half(in[r * QD + k]) : __half(0.f);
}

// in fp32 [R][C] -> out fp16 [C][RP], zero-padded rows beyond R
__global__ void transpose_cvt(const float* __restrict__ in, __half* __restrict__ out,
                              int R, int C, int RP) {
    __shared__ float t[32][33];
    int c0 = blockIdx.x * 32, r0 = blockIdx.y * 32;
    for (int dy = threadIdx.y; dy < 32; dy += 8) {
        int r = r0 + dy, c = c0 + threadIdx.x;
        t[dy][threadIdx.x] = (r < R && c < C) ? in[(size_t)r * C + c] : 0.f;
    }
    __syncthreads();
    for (int dy = threadIdx.y; dy < 32; dy += 8) {
        int oc = c0 + dy, orw = r0 + threadIdx.x;
        if (oc < C && orw < RP) out[(size_t)oc * RP + orw] = __float2half(t[threadIdx.x][dy]);
    }
}

// agg[i,f] = h[i,f] * dinv[i]^2 + bias[f]   (self-loop term + bias, overwrites dst)
__global__ void agg_init(const float* __restrict__ h, const float* __restrict__ dinv,
                         const float* __restrict__ bias, float* __restrict__ agg, int F) {
    int idx4 = blockIdx.x * blockDim.x + threadIdx.x;
    int fdiv4 = F >> 2;
    int total4 = NN * fdiv4;
    if (idx4 >= total4) return;
    int node = idx4 / fdiv4;
    int f4   = idx4 - node * fdiv4;
    float di = dinv[node];
    float s  = di * di;
    float4 hv = reinterpret_cast<const float4*>(h)[idx4];
    float4 bv = *reinterpret_cast<const float4*>(bias + (f4 << 2));
    float4 o;
    o.x = hv.x * s + bv.x;
    o.y = hv.y * s + bv.y;
    o.z = hv.z * s + bv.z;
    o.w = hv.w * s + bv.w;
    reinterpret_cast<float4*>(agg)[idx4] = o;
}

// Scatter-add: agg[dst] += h[src] * (dinv[src]*w*dinv[dst]) using vector reductions.
__global__ void edge_agg(const float* __restrict__ h, float* __restrict__ agg,
                         const int* __restrict__ src, const int* __restrict__ dst,
                         const float* __restrict__ ew, const float* __restrict__ dinv,
                         int E, int F) {
    int lanes = F >> 2;                       // float4 lanes per edge (128 or 64)
    int epb   = blockDim.x / lanes;           // edges per block
    int le    = threadIdx.x / lanes;
    int lane  = threadIdx.x - le * lanes;
    int e     = blockIdx.x * epb + le;
    if (e >= E) return;

    int s = src[e];
    int d = dst[e];
    float norm = dinv[s] * ew[e] * dinv[d];

    float4 hv = *reinterpret_cast<const float4*>(h + (size_t)s * F + (lane << 2));
    float* outp = agg + (size_t)d * F + (lane << 2);
    asm volatile("red.global.add.v4.f32 [%0], {%1, %2, %3, %4};"
                 :: "l"(outp),
                    "f"(hv.x * norm), "f"(hv.y * norm),
                    "f"(hv.z * norm), "f"(hv.w * norm)
                 : "memory");
}

// ---------------------------------------------------------------------------
// fp16 tensor-core GEMM: C[M,Ntot](fp32) = concat(A1,A2)[M,K](fp16) @ BT^T (+bias)
// BT fp16 [Ntot][K] (K-major). BM=BN=128, BK=64, 8 warps (2m x 4n), warp 64x32,
// mma m16n8k16.f16.f32. Smem: XOR-swizzled 128B rows (conflict-free ldmatrix),
// 2-stage cp.async. Requires: K % 8 == 0, K1 % 8 == 0, Ntot % 128 == 0,
// 16B-aligned rows (all call sites satisfy).
// ---------------------------------------------------------------------------
__global__ void __launch_bounds__(256, 2)
hgemm(const __half* __restrict__ A1, const __half* __restrict__ A2, int K1,
      const __half* __restrict__ BT, const float* __restrict__ bias,
      float* __restrict__ C, int M, int Ntot, int K)
{
    extern __shared__ __align__(128) char smem[];
    const uint32_t sb = smem_u32(smem);

    const int tid  = threadIdx.x;
    const int lane = tid & 31;
    const int warp = tid >> 5;
    const int wm   = warp >> 2;     // 0..1
    const int wn   = warp & 3;      // 0..3
    const int block_row = blockIdx.y * 128;
    const int block_col = blockIdx.x * 128;

    float acc[4][4][4];
    #pragma unroll
    for (int mt = 0; mt < 4; mt++)
        #pragma unroll
        for (int nt = 0; nt < 4; nt++)
            #pragma unroll
            for (int q = 0; q < 4; q++) acc[mt][nt][q] = 0.0f;

    // ldmatrix lane geometry
    const int lr = lane & 7;            // row within 8x8 matrix
    const int lm = (lane >> 3) & 1;     // +8 rows for matrices 1,3
    const int lc = lane >> 4;           // +1 chunk (8 halves) for matrices 2,3
    uint32_t a_off[4], a_x[4];
    #pragma unroll
    for (int mt = 0; mt < 4; mt++) {
        int row = wm * 64 + mt * 16 + lm * 8 + lr;
        a_off[mt] = (uint32_t)row * 128u;
        a_x[mt]   = (uint32_t)(row & 7);
    }
    uint32_t b_off[2], b_x[2];
    #pragma unroll
    for (int p = 0; p < 2; p++) {
        int row = wn * 32 + p * 16 + lm * 8 + lr;
        b_off[p] = (uint32_t)row * 128u;
        b_x[p]   = (uint32_t)(row & 7);
    }

    const int T = (K + 63) >> 6;

    auto load_tile = [&](int it) {
        int s = it & 1;
        uint32_t ab = sb + (uint32_t)s * 32768u;
        uint32_t bb = ab + 16384u;
        int k0 = it * 64;
        #pragma unroll
        for (int i = 0; i < 4; i++) {         // A: 128 rows x 8 chunks of 16B
            int id = tid + i * 256;
            int r = id >> 3, c = id & 7;
            int gm = block_row + r;
            int ge = k0 + c * 8;              // in halves
            const void* src = (const void*)A1;
            int sz = 0;
            if (gm < M && ge < K) {
                src = (ge < K1) ? (const void*)(A1 + (size_t)gm * K1 + ge)
                                : (const void*)(A2 + (size_t)gm * (K - K1) + (ge - K1));
                sz = 16;
            }
            cp_async16(ab + (uint32_t)(r * 128) + (uint32_t)(((c ^ (r & 7)) << 4)), src, sz);
        }
        #pragma unroll
        for (int i = 0; i < 4; i++) {         // B: 128 rows x 8 chunks of 16B
            int id = tid + i * 256;
            int n = id >> 3, c = id & 7;
            int ge = k0 + c * 8;
            const void* src = (const void*)BT;
            int sz = 0;
            if (ge < K) {
                src = (const void*)(BT + (size_t)(block_col + n) * K + ge);
                sz = 16;
            }
            cp_async16(bb + (uint32_t)(n * 128) + (uint32_t)(((c ^ (n & 7)) << 4)), src, sz);
        }
        asm volatile("cp.async.commit_group;" ::: "memory");
    };

    load_tile(0);
    if (T > 1) load_tile(1);

    for (int it = 0; it < T; it++) {
        if (it + 1 < T) asm volatile("cp.async.wait_group 1;" ::: "memory");
        else            asm volatile("cp.async.wait_group 0;" ::: "memory");
        __syncthreads();

        uint32_t ab = sb + (uint32_t)(it & 1) * 32768u;
        uint32_t bb = ab + 16384u;

        #pragma unroll
        for (int ks = 0; ks < 4; ks++) {
            unsigned a[4][4];
            #pragma unroll
            for (int mt = 0; mt < 4; mt++) {
                uint32_t ch = (uint32_t)(2 * ks) + (uint32_t)lc;
                LDSM_X4(a[mt][0], a[mt][1], a[mt][2], a[mt][3],
                        ab + a_off[mt] + ((ch ^ a_x[mt]) << 4));
            }
            unsigned b0[4], b1[4];
            #pragma unroll
            for (int p = 0; p < 2; p++) {
                uint32_t ch = (uint32_t)(2 * ks) + (uint32_t)lc;
                unsigned r0, r1, r2, r3;
                LDSM_X4(r0, r1, r2, r3, bb + b_off[p] + ((ch ^ b_x[p]) << 4));
                b0[2 * p] = r0; b0[2 * p + 1] = r1;
                b1[2 * p] = r2; b1[2 * p + 1] = r3;
            }
            #pragma unroll
            for (int mt = 0; mt < 4; mt++)
                #pragma unroll
                for (int nt = 0; nt < 4; nt++) {
                    asm volatile(
                        "mma.sync.aligned.m16n8k16.row.col.f32.f16.f16.f32 "
                        "{%0,%1,%2,%3}, {%4,%5,%6,%7}, {%8,%9}, {%0,%1,%2,%3};"
                        : "+f"(acc[mt][nt][0]), "+f"(acc[mt][nt][1]),
                          "+f"(acc[mt][nt][2]), "+f"(acc[mt][nt][3])
                        : "r"(a[mt][0]), "r"(a[mt][1]), "r"(a[mt][2]), "r"(a[mt][3]),
                          "r"(b0[nt]), "r"(b1[nt]));
                }
        }
        __syncthreads();
        if (it + 2 < T) load_tile(it + 2);
    }

    // ---- epilogue ----
    #pragma unroll
    for (int mt = 0; mt < 4; mt++) {
        int r0 = block_row + wm * 64 + mt * 16 + (lane >> 2);
        #pragma unroll
        for (int nt = 0; nt < 4; nt++) {
            int c = block_col + wn * 32 + nt * 8 + 2 * (lane & 3);
            if (r0 < M) {
                float2 v = make_float2(acc[mt][nt][0], acc[mt][nt][1]);
                if (bias) { v.x += bias[c]; v.y += bias[c + 1]; }
                *reinterpret_cast<float2*>(C + (size_t)r0 * Ntot + c) = v;
            }
            int r1 = r0 + 8;
            if (r1 < M) {
                float2 v = make_float2(acc[mt][nt][2], acc[mt][nt][3]);
                if (bias) { v.x += bias[c]; v.y += bias[c + 1]; }
                *reinterpret_cast<float2*>(C + (size_t)r1 * Ntot + c) = v;
            }
        }
    }
}

#define HGEMM_SMEM 65536

static void gemm_h(const __half* A1, const __half* A2, int K1,
                   const __half* BT, const float* bias, float* C,
                   int M, int Ntot, int K) {
    dim3 grid(Ntot / 128, (M + 127) / 128);
    hgemm<<<grid, 256, HGEMM_SMEM>>>(A1, A2, K1, BT, bias, C, M, Ntot, K);
}

// ---------------------------------------------------------------------------
// Launch orchestration
// ---------------------------------------------------------------------------
extern "C" void kernel_launch(void* const* d_in, const int* in_sizes, int n_in,
                              void* d_out, int out_size) {
    const float* x_RNA     = (const float*)d_in[0];
    const float* x_ADT     = (const float*)d_in[1];
    const int*   sim_ei    = (const int*)  d_in[2];   // [2,E]: row0=src, row1=dst
    const float* sim_ew    = (const float*)d_in[3];
    const int*   dist_ei   = (const int*)  d_in[4];
    const float* dist_ew   = (const float*)d_in[5];
    const int*   common_ei = (const int*)  d_in[6];
    const float* common_ew = (const float*)d_in[7];
    const float* W_rna1    = (const float*)d_in[8];
    const float* b_rna1    = (const float*)d_in[9];
    const float* W_rna2    = (const float*)d_in[10];
    const float* b_rna2    = (const float*)d_in[11];
    const float* W_p3      = (const float*)d_in[12];
    const float* b_p3      = (const float*)d_in[13];
    const float* W_sim     = (const float*)d_in[14];
    const float* b_sim     = (const float*)d_in[15];
    const float* W_dist    = (const float*)d_in[16];
    const float* b_dist    = (const float*)d_in[17];
    const float* W_f1      = (const float*)d_in[18];
    const float* b_f1      = (const float*)d_in[19];
    const float* W_f2      = (const float*)d_in[20];
    const float* b_f2      = (const float*)d_in[21];

    float* out = (float*)d_out;
    const size_t SEC = (size_t)NN * OUTD;
    float* out_xsim  = out;
    float* out_xdist = out + SEC;
    float* out_fused = out + 2 * SEC;
    float* out_fpro  = out + 3 * SEC;
    float* out_pro   = out + 4 * SEC;

    __half *ah, *adth, *xsh, *xdh, *wt;
    float  *h, *xs, *xd, *dinv;
    cudaGetSymbolAddress((void**)&ah,   g_ah);
    cudaGetSymbolAddress((void**)&adth, g_adth);
    cudaGetSymbolAddress((void**)&xsh,  g_xsh);
    cudaGetSymbolAddress((void**)&xdh,  g_xdh);
    cudaGetSymbolAddress((void**)&wt,   g_wth);
    cudaGetSymbolAddress((void**)&h,    g_h);
    cudaGetSymbolAddress((void**)&xs,   g_xs);
    cudaGetSymbolAddress((void**)&xd,   g_xd);
    cudaGetSymbolAddress((void**)&dinv, g_dinv);
    float* dinv_sim    = dinv;
    float* dinv_dist   = dinv + NN;
    float* dinv_common = dinv + 2 * NN;

    cudaFuncSetAttribute(hgemm, cudaFuncAttributeMaxDynamicSharedMemorySize, HGEMM_SMEM);

    // ---- degree normalization for all three graphs ----
    fill_ones<<<(3 * NN + 255) / 256, 256>>>(dinv, 3 * NN);
    deg_accum<<<(EE + 255) / 256, 256>>>(sim_ei + EE,    sim_ew,    dinv_sim,    EE);
    deg_accum<<<(EE + 255) / 256, 256>>>(dist_ei + EE,   dist_ew,   dinv_dist,   EE);
    deg_accum<<<(EE + 255) / 256, 256>>>(common_ei + EE, common_ew, dinv_common, EE);
    rsqrt_inplace<<<(3 * NN + 255) / 256, 256>>>(dinv, 3 * NN);

    // ---- operand conversion: weights (transpose to [N][K] fp16) + A matrices ----
    dim3 tb(32, 8);
    transpose_cvt<<<dim3((HIDDEN + 31) / 32, (INC  + 31) / 32), tb>>>(W_rna1, wt + WT_RNA1, INC,    HIDDEN, INC);
    transpose_cvt<<<dim3((HIDDEN + 31) / 32, (INC  + 31) / 32), tb>>>(W_rna2, wt + WT_RNA2, INC,    HIDDEN, INC);
    transpose_cvt<<<dim3((OUTD + 31) / 32, (HIDDEN + 31) / 32), tb>>>(W_sim,  wt + WT_SIM,  HIDDEN, OUTD,   HIDDEN);
    transpose_cvt<<<dim3((OUTD + 31) / 32, (HIDDEN + 31) / 32), tb>>>(W_dist, wt + WT_DIST, HIDDEN, OUTD,   HIDDEN);
    transpose_cvt<<<dim3((OUTD + 31) / 32, (QPAD   + 31) / 32), tb>>>(W_p3,   wt + WT_P3,   QD,     OUTD,   QPAD);
    transpose_cvt<<<dim3((OUTD + 31) / 32, (2*OUTD + 31) / 32), tb>>>(W_f1,   wt + WT_F1,   2*OUTD, OUTD,   2*OUTD);
    transpose_cvt<<<dim3((OUTD + 31) / 32, (2*OUTD + 31) / 32), tb>>>(W_f2,   wt + WT_F2,   2*OUTD, OUTD,   2*OUTD);

    cvt_fp16<<<(NN * INC / 4 + 255) / 256, 256>>>(x_RNA, ah, NN * INC / 4);
    pad_adt<<<(NN * QPAD + 255) / 256, 256>>>(x_ADT, adth);

    const int grid512 = (NN * (HIDDEN / 4) + 255) / 256;
    const int grid256 = (NN * (OUTD / 4) + 255) / 256;
    const int egrid512 = (EE + 1) / 2;   // 2 edges/block @ F=512, 256 threads
    const int egrid256 = (EE + 3) / 4;   // 4 edges/block @ F=256
    const int c512 = (NN * HIDDEN / 4 + 255) / 256;
    const int c256 = (NN * OUTD / 4 + 255) / 256;

    // ---- pro = gcn(x_ADT, common; W_p3, b_p3) -> d_out[4] ----
    gemm_h(adth, adth, QPAD, wt + WT_P3, nullptr, h, NN, OUTD, QPAD);
    agg_init<<<grid256, 256>>>(h, dinv_common, b_p3, out_pro, OUTD);
    edge_agg<<<egrid256, 256>>>(h, out_pro, common_ei, common_ei + EE, common_ew, dinv_common, EE, OUTD);

    // ---- Layer 1, sim: xs = relu(gcn(x_RNA, sim; W_rna1, b_rna1)) ----
    gemm_h(ah, ah, INC, wt + WT_RNA1, nullptr, h, NN, HIDDEN, INC);
    agg_init<<<grid512, 256>>>(h, dinv_sim, b_rna1, xs, HIDDEN);
    edge_agg<<<egrid512, 256>>>(h, xs, sim_ei, sim_ei + EE, sim_ew, dinv_sim, EE, HIDDEN);
    relu_cvt<<<c512, 256>>>(xs, xsh, NN * HIDDEN / 4);

    // ---- Layer 1, dist: xd = relu(gcn(x_RNA, dist; W_rna2, b_rna2)) ----
    gemm_h(ah, ah, INC, wt + WT_RNA2, nullptr, h, NN, HIDDEN, INC);
    agg_init<<<grid512, 256>>>(h, dinv_dist, b_rna2, xd, HIDDEN);
    edge_agg<<<egrid512, 256>>>(h, xd, dist_ei, dist_ei + EE, dist_ew, dinv_dist, EE, HIDDEN);
    relu_cvt<<<c512, 256>>>(xd, xdh, NN * HIDDEN / 4);

    // ---- Layer 2: x_sim = gcn(xs, sim; W_sim, b_sim) -> d_out[0] ----
    gemm_h(xsh, xsh, HIDDEN, wt + WT_SIM, nullptr, h, NN, OUTD, HIDDEN);
    agg_init<<<grid256, 256>>>(h, dinv_sim, b_sim, out_xsim, OUTD);
    edge_agg<<<egrid256, 256>>>(h, out_xsim, sim_ei, sim_ei + EE, sim_ew, dinv_sim, EE, OUTD);

    // ---- Layer 2: x_dist = gcn(xd, dist; W_dist, b_dist) -> d_out[1] ----
    gemm_h(xdh, xdh, HIDDEN, wt + WT_DIST, nullptr, h, NN, OUTD, HIDDEN);
    agg_init<<<grid256, 256>>>(h, dinv_dist, b_dist, out_xdist, OUTD);
    edge_agg<<<egrid256, 256>>>(h, out_xdist, dist_ei, dist_ei + EE, dist_ew, dinv_dist, EE, OUTD);

    // ---- fused = concat(x_sim, x_dist) @ W_f1 + b_f1 -> d_out[2] (K-split) ----
    cvt_fp16<<<c256, 256>>>(out_xsim,  xsh, NN * OUTD / 4);
    cvt_fp16<<<c256, 256>>>(out_xdist, xdh, NN * OUTD / 4);
    gemm_h(xsh, xdh, OUTD, wt + WT_F1, b_f1, out_fused, NN, OUTD, 2 * OUTD);

    // ---- fused_pro = concat(fused, pro) @ W_f2 + b_f2 -> d_out[3] ----
    cvt_fp16<<<c256, 256>>>(out_fused, xsh, NN * OUTD / 4);
    cvt_fp16<<<c256, 256>>>(out_pro,   xdh, NN * OUTD / 4);
    gemm_h(xsh, xdh, OUTD, wt + WT_F2, b_f2, out_fpro, NN, OUTD, 2 * OUTD);
}

// round 14
// speedup vs baseline: 1.4818x; 1.4815x over previous
#include <cuda_runtime.h>
#include <cuda_fp16.h>
#include <cstdint>
#include <cstddef>

// Problem dims (fixed by the reference)
#define NN     20000
#define EE     320000
#define INC    2000
#define HIDDEN 512
#define OUTD   256
#define QD     100
#define QPAD   128     // x_ADT K padded to 128 for 16B-aligned fp16 rows

// ---------------------------------------------------------------------------
// Scratch (device globals; no dynamic allocation allowed)
// ---------------------------------------------------------------------------
__device__ __align__(16) __half g_ah  [NN * INC];      // fp16 x_RNA (80MB)
__device__ __align__(16) __half g_adth[NN * QPAD];     // fp16 x_ADT padded
__device__ __align__(16) __half g_xsh [NN * HIDDEN];   // fp16 xs / fusion A1
__device__ __align__(16) __half g_xdh [NN * HIDDEN];   // fp16 xd / fusion A2
__device__ __align__(16) __half g_proh[NN * OUTD];     // fp16 pro (fusion-2 A2)
__device__ __align__(16) __half g_wth [2605056];       // fp16 transposed weights [N][K]
__device__ float g_h  [NN * HIDDEN];   // GEMM outputs (pre-aggregation, fp32)
__device__ float g_dinv[3 * NN];       // deg^-0.5 for sim / dist / common

// CSR scratch (per graph: sim / dist / common)
__device__ int   g_cnt [3 * NN];
__device__ int   g_offs[3 * (NN + 1)];
__device__ int   g_cur [3 * NN];
__device__ int   g_csrc[3 * EE];
__device__ float g_ccoef[3 * EE];

// weight segment offsets in g_wth (halves; all multiples of 8 -> 16B aligned)
#define WT_RNA1 0
#define WT_RNA2 1024000
#define WT_SIM  2048000
#define WT_DIST 2179072
#define WT_P3   2310144
#define WT_F1   2342912
#define WT_F2   2473984

// ---------------------------------------------------------------------------
// PTX helpers
// ---------------------------------------------------------------------------
__device__ __forceinline__ uint32_t smem_u32(const void* p) {
    uint32_t a;
    asm("{ .reg .u64 t; cvta.to.shared.u64 t, %1; cvt.u32.u64 %0, t; }" : "=r"(a) : "l"(p));
    return a;
}
__device__ __forceinline__ void cp_async16(uint32_t sa, const void* g, int src_size) {
    asm volatile("cp.async.cg.shared.global [%0], [%1], 16, %2;"
                 :: "r"(sa), "l"(g), "r"(src_size));
}
#define LDSM_X4(r0, r1, r2, r3, addr) \
    asm volatile("ldmatrix.sync.aligned.m8n8.x4.shared.b16 {%0,%1,%2,%3}, [%4];" \
                 : "=r"(r0), "=r"(r1), "=r"(r2), "=r"(r3) : "r"(addr))

// ---------------------------------------------------------------------------
// Degree + CSR construction
// ---------------------------------------------------------------------------
__global__ void init_deg_cnt(float* __restrict__ deg, int* __restrict__ cnt, int n) {
    int i = blockIdx.x * blockDim.x + threadIdx.x;
    if (i < n) { deg[i] = 1.0f; cnt[i] = 0; }   // self-loop weight 1
}

__global__ void deg_count(const int* __restrict__ dst, const float* __restrict__ w,
                          float* __restrict__ deg, int* __restrict__ cnt, int E) {
    int e = blockIdx.x * blockDim.x + threadIdx.x;
    if (e >= E) return;
    int d = dst[e];
    atomicAdd(&deg[d], w[e]);
    atomicAdd(&cnt[d], 1);
}

__global__ void rsqrt_inplace(float* __restrict__ p, int n) {
    int i = blockIdx.x * blockDim.x + threadIdx.x;
    if (i < n) p[i] = rsqrtf(p[i]);   // deg >= 1 always
}

// Exclusive scan of cnt -> offs (+ copy to cursor). One block per graph.
__global__ void scan_offsets(const int* __restrict__ cnt, int* __restrict__ offs,
                             int* __restrict__ cur) {
    const int g = blockIdx.x;
    const int* c = cnt + g * NN;
    int* o   = offs + g * (NN + 1);
    int* cu  = cur  + g * NN;
    __shared__ int sh[1024];
    __shared__ int carry_sh;
    int t = threadIdx.x;
    if (t == 0) carry_sh = 0;
    __syncthreads();
    for (int base = 0; base < NN; base += 1024) {
        int v = (base + t < NN) ? c[base + t] : 0;
        sh[t] = v;
        __syncthreads();
        #pragma unroll
        for (int off = 1; off < 1024; off <<= 1) {
            int add = (t >= off) ? sh[t - off] : 0;
            __syncthreads();
            sh[t] += add;
            __syncthreads();
        }
        int carry = carry_sh;
        int excl  = carry + sh[t] - v;
        if (base + t < NN) { o[base + t] = excl; cu[base + t] = excl; }
        __syncthreads();
        if (t == 1023) carry_sh = carry + sh[1023];
        __syncthreads();
    }
    if (t == 0) o[NN] = carry_sh;
}

// Fill CSR: for each edge, slot under its dst; precompute normalization coef.
__global__ void csr_fill(const int* __restrict__ src, const int* __restrict__ dst,
                         const float* __restrict__ ew, const float* __restrict__ dinv,
                         int* __restrict__ cur, int* __restrict__ csrc,
                         float* __restrict__ ccoef, int E) {
    int e = blockIdx.x * blockDim.x + threadIdx.x;
    if (e >= E) return;
    int s = src[e], d = dst[e];
    int pos = atomicAdd(&cur[d], 1);
    csrc[pos]  = s;
    ccoef[pos] = dinv[s] * ew[e] * dinv[d];
}

// ---------------------------------------------------------------------------
// GCN gather: out[d] = h[d]*dinv[d]^2 + bias + sum_in-edges coef*h[src]
// One node per (F/4)-lane group; 256-thread blocks. Optional ReLU, fp32/fp16 out.
// ---------------------------------------------------------------------------
template <int F, bool RELU, bool OUT32, bool OUT16>
__global__ void gcn_gather(const float* __restrict__ h,
                           const int* __restrict__ offs,
                           const int* __restrict__ csrc,
                           const float* __restrict__ ccoef,
                           const float* __restrict__ dinv,
                           const float* __restrict__ bias,
                           float* __restrict__ o32, __half* __restrict__ o16) {
    constexpr int LANES = F / 4;
    constexpr int NPB   = 256 / LANES;
    int node = blockIdx.x * NPB + threadIdx.x / LANES;
    int lane = threadIdx.x & (LANES - 1);
    if (node >= NN) return;

    int beg = offs[node], end = offs[node + 1];
    float di = dinv[node];
    float sc = di * di;
    float4 acc = *reinterpret_cast<const float4*>(h + (size_t)node * F + lane * 4);
    float4 bv  = *reinterpret_cast<const float4*>(bias + lane * 4);
    acc.x = acc.x * sc + bv.x;
    acc.y = acc.y * sc + bv.y;
    acc.z = acc.z * sc + bv.z;
    acc.w = acc.w * sc + bv.w;

    int j = beg;
    for (; j + 2 <= end; j += 2) {          // 2x unroll for MLP
        int   s0 = csrc[j],     s1 = csrc[j + 1];
        float c0 = ccoef[j],    c1 = ccoef[j + 1];
        float4 h0 = *reinterpret_cast<const float4*>(h + (size_t)s0 * F + lane * 4);
        float4 h1 = *reinterpret_cast<const float4*>(h + (size_t)s1 * F + lane * 4);
        acc.x += h0.x * c0 + h1.x * c1;
        acc.y += h0.y * c0 + h1.y * c1;
        acc.z += h0.z * c0 + h1.z * c1;
        acc.w += h0.w * c0 + h1.w * c1;
    }
    if (j < end) {
        int   s0 = csrc[j];
        float c0 = ccoef[j];
        float4 h0 = *reinterpret_cast<const float4*>(h + (size_t)s0 * F + lane * 4);
        acc.x += h0.x * c0; acc.y += h0.y * c0;
        acc.z += h0.z * c0; acc.w += h0.w * c0;
    }

    if (RELU) {
        acc.x = fmaxf(acc.x, 0.f); acc.y = fmaxf(acc.y, 0.f);
        acc.z = fmaxf(acc.z, 0.f); acc.w = fmaxf(acc.w, 0.f);
    }
    if (OUT32)
        *reinterpret_cast<float4*>(o32 + (size_t)node * F + lane * 4) = acc;
    if (OUT16) {
        __half2 lo = __floats2half2_rn(acc.x, acc.y);
        __half2 hi = __floats2half2_rn(acc.z, acc.w);
        __half2* p = reinterpret_cast<__half2*>(o16 + (size_t)node * F + lane * 4);
        p[0] = lo; p[1] = hi;
    }
}

// ---------------------------------------------------------------------------
// Elementwise conversion kernels
// ---------------------------------------------------------------------------
__global__ void cvt_fp16(const float* __restrict__ in, __half* __restrict__ out, int n4) {
    int i = blockIdx.x * blockDim.x + threadIdx.x;
    if (i >= n4) return;
    float4 v = reinterpret_cast<const float4*>(in)[i];
    reinterpret_cast<__half2*>(out)[2 * i]     = __floats2half2_rn(v.x, v.y);
    reinterpret_cast<__half2*>(out)[2 * i + 1] = __floats2half2_rn(v.z, v.w);
}

__global__ void pad_adt(const float* __restrict__ in, __half* __restrict__ out) {
    int idx = blockIdx.x * blockDim.x + threadIdx.x;
    if (idx >= NN * QPAD) return;
    int r = idx >> 7, k = idx & (QPAD - 1);
    out[idx] = (k < QD) ? __float2half(in[r * QD + k]) : __half(0.f);
}

// in fp32 [R][C] -> out fp16 [C][RP], zero-padded rows beyond R
__global__ void transpose_cvt(const float* __restrict__ in, __half* __restrict__ out,
                              int R, int C, int RP) {
    __shared__ float t[32][33];
    int c0 = blockIdx.x * 32, r0 = blockIdx.y * 32;
    for (int dy = threadIdx.y; dy < 32; dy += 8) {
        int r = r0 + dy, c = c0 + threadIdx.x;
        t[dy][threadIdx.x] = (r < R && c < C) ? in[(size_t)r * C + c] : 0.f;
    }
    __syncthreads();
    for (int dy = threadIdx.y; dy < 32; dy += 8) {
        int oc = c0 + dy, orw = r0 + threadIdx.x;
        if (oc < C && orw < RP) out[(size_t)oc * RP + orw] = __float2half(t[threadIdx.x][dy]);
    }
}

// ---------------------------------------------------------------------------
// fp16 tensor-core GEMM (unchanged from R13): C[M,Ntot](fp32) =
// concat(A1,A2)[M,K](fp16) @ BT^T (+bias). BT fp16 [Ntot][K] K-major.
// BM=BN=128, BK=64, 8 warps, mma m16n8k16, XOR-swizzled smem, 2-stage cp.async.
// ---------------------------------------------------------------------------
__global__ void __launch_bounds__(256, 2)
hgemm(const __half* __restrict__ A1, const __half* __restrict__ A2, int K1,
      const __half* __restrict__ BT, const float* __restrict__ bias,
      float* __restrict__ C, int M, int Ntot, int K)
{
    extern __shared__ __align__(128) char smem[];
    const uint32_t sb = smem_u32(smem);

    const int tid  = threadIdx.x;
    const int lane = tid & 31;
    const int warp = tid >> 5;
    const int wm   = warp >> 2;
    const int wn   = warp & 3;
    const int block_row = blockIdx.y * 128;
    const int block_col = blockIdx.x * 128;

    float acc[4][4][4];
    #pragma unroll
    for (int mt = 0; mt < 4; mt++)
        #pragma unroll
        for (int nt = 0; nt < 4; nt++)
            #pragma unroll
            for (int q = 0; q < 4; q++) acc[mt][nt][q] = 0.0f;

    const int lr = lane & 7;
    const int lm = (lane >> 3) & 1;
    const int lc = lane >> 4;
    uint32_t a_off[4], a_x[4];
    #pragma unroll
    for (int mt = 0; mt < 4; mt++) {
        int row = wm * 64 + mt * 16 + lm * 8 + lr;
        a_off[mt] = (uint32_t)row * 128u;
        a_x[mt]   = (uint32_t)(row & 7);
    }
    uint32_t b_off[2], b_x[2];
    #pragma unroll
    for (int p = 0; p < 2; p++) {
        int row = wn * 32 + p * 16 + lm * 8 + lr;
        b_off[p] = (uint32_t)row * 128u;
        b_x[p]   = (uint32_t)(row & 7);
    }

    const int T = (K + 63) >> 6;

    auto load_tile = [&](int it) {
        int s = it & 1;
        uint32_t ab = sb + (uint32_t)s * 32768u;
        uint32_t bb = ab + 16384u;
        int k0 = it * 64;
        #pragma unroll
        for (int i = 0; i < 4; i++) {
            int id = tid + i * 256;
            int r = id >> 3, c = id & 7;
            int gm = block_row + r;
            int ge = k0 + c * 8;
            const void* src = (const void*)A1;
            int sz = 0;
            if (gm < M && ge < K) {
                src = (ge < K1) ? (const void*)(A1 + (size_t)gm * K1 + ge)
                                : (const void*)(A2 + (size_t)gm * (K - K1) + (ge - K1));
                sz = 16;
            }
            cp_async16(ab + (uint32_t)(r * 128) + (uint32_t)(((c ^ (r & 7)) << 4)), src, sz);
        }
        #pragma unroll
        for (int i = 0; i < 4; i++) {
            int id = tid + i * 256;
            int n = id >> 3, c = id & 7;
            int ge = k0 + c * 8;
            const void* src = (const void*)BT;
            int sz = 0;
            if (ge < K) {
                src = (const void*)(BT + (size_t)(block_col + n) * K + ge);
                sz = 16;
            }
            cp_async16(bb + (uint32_t)(n * 128) + (uint32_t)(((c ^ (n & 7)) << 4)), src, sz);
        }
        asm volatile("cp.async.commit_group;" ::: "memory");
    };

    load_tile(0);
    if (T > 1) load_tile(1);

    for (int it = 0; it < T; it++) {
        if (it + 1 < T) asm volatile("cp.async.wait_group 1;" ::: "memory");
        else            asm volatile("cp.async.wait_group 0;" ::: "memory");
        __syncthreads();

        uint32_t ab = sb + (uint32_t)(it & 1) * 32768u;
        uint32_t bb = ab + 16384u;

        #pragma unroll
        for (int ks = 0; ks < 4; ks++) {
            unsigned a[4][4];
            #pragma unroll
            for (int mt = 0; mt < 4; mt++) {
                uint32_t ch = (uint32_t)(2 * ks) + (uint32_t)lc;
                LDSM_X4(a[mt][0], a[mt][1], a[mt][2], a[mt][3],
                        ab + a_off[mt] + ((ch ^ a_x[mt]) << 4));
            }
            unsigned b0[4], b1[4];
            #pragma unroll
            for (int p = 0; p < 2; p++) {
                uint32_t ch = (uint32_t)(2 * ks) + (uint32_t)lc;
                unsigned r0, r1, r2, r3;
                LDSM_X4(r0, r1, r2, r3, bb + b_off[p] + ((ch ^ b_x[p]) << 4));
                b0[2 * p] = r0; b0[2 * p + 1] = r1;
                b1[2 * p] = r2; b1[2 * p + 1] = r3;
            }
            #pragma unroll
            for (int mt = 0; mt < 4; mt++)
                #pragma unroll
                for (int nt = 0; nt < 4; nt++) {
                    asm volatile(
                        "mma.sync.aligned.m16n8k16.row.col.f32.f16.f16.f32 "
                        "{%0,%1,%2,%3}, {%4,%5,%6,%7}, {%8,%9}, {%0,%1,%2,%3};"
                        : "+f"(acc[mt][nt][0]), "+f"(acc[mt][nt][1]),
                          "+f"(acc[mt][nt][2]), "+f"(acc[mt][nt][3])
                        : "r"(a[mt][0]), "r"(a[mt][1]), "r"(a[mt][2]), "r"(a[mt][3]),
                          "r"(b0[nt]), "r"(b1[nt]));
                }
        }
        __syncthreads();
        if (it + 2 < T) load_tile(it + 2);
    }

    #pragma unroll
    for (int mt = 0; mt < 4; mt++) {
        int r0 = block_row + wm * 64 + mt * 16 + (lane >> 2);
        #pragma unroll
        for (int nt = 0; nt < 4; nt++) {
            int c = block_col + wn * 32 + nt * 8 + 2 * (lane & 3);
            if (r0 < M) {
                float2 v = make_float2(acc[mt][nt][0], acc[mt][nt][1]);
                if (bias) { v.x += bias[c]; v.y += bias[c + 1]; }
                *reinterpret_cast<float2*>(C + (size_t)r0 * Ntot + c) = v;
            }
            int r1 = r0 + 8;
            if (r1 < M) {
                float2 v = make_float2(acc[mt][nt][2], acc[mt][nt][3]);
                if (bias) { v.x += bias[c]; v.y += bias[c + 1]; }
                *reinterpret_cast<float2*>(C + (size_t)r1 * Ntot + c) = v;
            }
        }
    }
}

#define HGEMM_SMEM 65536

static void gemm_h(const __half* A1, const __half* A2, int K1,
                   const __half* BT, const float* bias, float* C,
                   int M, int Ntot, int K) {
    dim3 grid(Ntot / 128, (M + 127) / 128);
    hgemm<<<grid, 256, HGEMM_SMEM>>>(A1, A2, K1, BT, bias, C, M, Ntot, K);
}

// ---------------------------------------------------------------------------
// Launch orchestration
// ---------------------------------------------------------------------------
extern "C" void kernel_launch(void* const* d_in, const int* in_sizes, int n_in,
                              void* d_out, int out_size) {
    const float* x_RNA     = (const float*)d_in[0];
    const float* x_ADT     = (const float*)d_in[1];
    const int*   sim_ei    = (const int*)  d_in[2];   // [2,E]: row0=src, row1=dst
    const float* sim_ew    = (const float*)d_in[3];
    const int*   dist_ei   = (const int*)  d_in[4];
    const float* dist_ew   = (const float*)d_in[5];
    const int*   common_ei = (const int*)  d_in[6];
    const float* common_ew = (const float*)d_in[7];
    const float* W_rna1    = (const float*)d_in[8];
    const float* b_rna1    = (const float*)d_in[9];
    const float* W_rna2    = (const float*)d_in[10];
    const float* b_rna2    = (const float*)d_in[11];
    const float* W_p3      = (const float*)d_in[12];
    const float* b_p3      = (const float*)d_in[13];
    const float* W_sim     = (const float*)d_in[14];
    const float* b_sim     = (const float*)d_in[15];
    const float* W_dist    = (const float*)d_in[16];
    const float* b_dist    = (const float*)d_in[17];
    const float* W_f1      = (const float*)d_in[18];
    const float* b_f1      = (const float*)d_in[19];
    const float* W_f2      = (const float*)d_in[20];
    const float* b_f2      = (const float*)d_in[21];

    float* out = (float*)d_out;
    const size_t SEC = (size_t)NN * OUTD;
    float* out_xsim  = out;
    float* out_xdist = out + SEC;
    float* out_fused = out + 2 * SEC;
    float* out_fpro  = out + 3 * SEC;
    float* out_pro   = out + 4 * SEC;

    __half *ah, *adth, *xsh, *xdh, *proh, *wt;
    float  *h, *dinv, *ccoef;
    int    *cnt, *offs, *cur, *csrc;
    cudaGetSymbolAddress((void**)&ah,    g_ah);
    cudaGetSymbolAddress((void**)&adth,  g_adth);
    cudaGetSymbolAddress((void**)&xsh,   g_xsh);
    cudaGetSymbolAddress((void**)&xdh,   g_xdh);
    cudaGetSymbolAddress((void**)&proh,  g_proh);
    cudaGetSymbolAddress((void**)&wt,    g_wth);
    cudaGetSymbolAddress((void**)&h,     g_h);
    cudaGetSymbolAddress((void**)&dinv,  g_dinv);
    cudaGetSymbolAddress((void**)&cnt,   g_cnt);
    cudaGetSymbolAddress((void**)&offs,  g_offs);
    cudaGetSymbolAddress((void**)&cur,   g_cur);
    cudaGetSymbolAddress((void**)&csrc,  g_csrc);
    cudaGetSymbolAddress((void**)&ccoef, g_ccoef);

    float* dinv_s = dinv;
    float* dinv_d = dinv + NN;
    float* dinv_c = dinv + 2 * NN;

    cudaFuncSetAttribute(hgemm, cudaFuncAttributeMaxDynamicSharedMemorySize, HGEMM_SMEM);

    const int eg = (EE + 255) / 256;

    // ---- degree + CSR construction for all three graphs ----
    init_deg_cnt<<<(3 * NN + 255) / 256, 256>>>(dinv, cnt, 3 * NN);
    deg_count<<<eg, 256>>>(sim_ei + EE,    sim_ew,    dinv_s, cnt,          EE);
    deg_count<<<eg, 256>>>(dist_ei + EE,   dist_ew,   dinv_d, cnt + NN,     EE);
    deg_count<<<eg, 256>>>(common_ei + EE, common_ew, dinv_c, cnt + 2 * NN, EE);
    rsqrt_inplace<<<(3 * NN + 255) / 256, 256>>>(dinv, 3 * NN);
    scan_offsets<<<3, 1024>>>(cnt, offs, cur);
    csr_fill<<<eg, 256>>>(sim_ei,    sim_ei + EE,    sim_ew,    dinv_s, cur,
                          csrc,          ccoef,          EE);
    csr_fill<<<eg, 256>>>(dist_ei,   dist_ei + EE,   dist_ew,   dinv_d, cur + NN,
                          csrc + EE,     ccoef + EE,     EE);
    csr_fill<<<eg, 256>>>(common_ei, common_ei + EE, common_ew, dinv_c, cur + 2 * NN,
                          csrc + 2 * EE, ccoef + 2 * EE, EE);

    const int* offs_s = offs;
    const int* offs_d = offs + (NN + 1);
    const int* offs_c = offs + 2 * (NN + 1);

    // ---- operand conversion: weights (transpose to [N][K] fp16) + A matrices ----
    dim3 tb(32, 8);
    transpose_cvt<<<dim3((HIDDEN + 31) / 32, (INC  + 31) / 32), tb>>>(W_rna1, wt + WT_RNA1, INC,    HIDDEN, INC);
    transpose_cvt<<<dim3((HIDDEN + 31) / 32, (INC  + 31) / 32), tb>>>(W_rna2, wt + WT_RNA2, INC,    HIDDEN, INC);
    transpose_cvt<<<dim3((OUTD + 31) / 32, (HIDDEN + 31) / 32), tb>>>(W_sim,  wt + WT_SIM,  HIDDEN, OUTD,   HIDDEN);
    transpose_cvt<<<dim3((OUTD + 31) / 32, (HIDDEN + 31) / 32), tb>>>(W_dist, wt + WT_DIST, HIDDEN, OUTD,   HIDDEN);
    transpose_cvt<<<dim3((OUTD + 31) / 32, (QPAD   + 31) / 32), tb>>>(W_p3,   wt + WT_P3,   QD,     OUTD,   QPAD);
    transpose_cvt<<<dim3((OUTD + 31) / 32, (2*OUTD + 31) / 32), tb>>>(W_f1,   wt + WT_F1,   2*OUTD, OUTD,   2*OUTD);
    transpose_cvt<<<dim3((OUTD + 31) / 32, (2*OUTD + 31) / 32), tb>>>(W_f2,   wt + WT_F2,   2*OUTD, OUTD,   2*OUTD);

    cvt_fp16<<<(NN * INC / 4 + 255) / 256, 256>>>(x_RNA, ah, NN * INC / 4);
    pad_adt<<<(NN * QPAD + 255) / 256, 256>>>(x_ADT, adth);

    const int c256 = (NN * OUTD / 4 + 255) / 256;

    // ---- pro = gcn(x_ADT, common; W_p3, b_p3) -> d_out[4] (+fp16 for f2) ----
    gemm_h(adth, adth, QPAD, wt + WT_P3, nullptr, h, NN, OUTD, QPAD);
    gcn_gather<OUTD, false, true, true><<<NN / 4, 256>>>(
        h, offs_c, csrc + 2 * EE, ccoef + 2 * EE, dinv_c, b_p3, out_pro, proh);

    // ---- Layer 1, sim: xsh = fp16(relu(gcn(x_RNA, sim))) ----
    gemm_h(ah, ah, INC, wt + WT_RNA1, nullptr, h, NN, HIDDEN, INC);
    gcn_gather<HIDDEN, true, false, true><<<NN / 2, 256>>>(
        h, offs_s, csrc, ccoef, dinv_s, b_rna1, nullptr, xsh);

    // ---- Layer 1, dist: xdh = fp16(relu(gcn(x_RNA, dist))) ----
    gemm_h(ah, ah, INC, wt + WT_RNA2, nullptr, h, NN, HIDDEN, INC);
    gcn_gather<HIDDEN, true, false, true><<<NN / 2, 256>>>(
        h, offs_d, csrc + EE, ccoef + EE, dinv_d, b_rna2, nullptr, xdh);

    // ---- Layer 2: x_sim -> d_out[0] (+fp16 into xsh for f1) ----
    gemm_h(xsh, xsh, HIDDEN, wt + WT_SIM, nullptr, h, NN, OUTD, HIDDEN);
    gcn_gather<OUTD, false, true, true><<<NN / 4, 256>>>(
        h, offs_s, csrc, ccoef, dinv_s, b_sim, out_xsim, xsh);

    // ---- Layer 2: x_dist -> d_out[1] (+fp16 into xdh for f1) ----
    gemm_h(xdh, xdh, HIDDEN, wt + WT_DIST, nullptr, h, NN, OUTD, HIDDEN);
    gcn_gather<OUTD, false, true, true><<<NN / 4, 256>>>(
        h, offs_d, csrc + EE, ccoef + EE, dinv_d, b_dist, out_xdist, xdh);

    // ---- fused = concat(x_sim, x_dist) @ W_f1 + b_f1 -> d_out[2] (K-split) ----
    gemm_h(xsh, xdh, OUTD, wt + WT_F1, b_f1, out_fused, NN, OUTD, 2 * OUTD);

    // ---- fused_pro = concat(fused, pro) @ W_f2 + b_f2 -> d_out[3] ----
    cvt_fp16<<<c256, 256>>>(out_fused, xsh, NN * OUTD / 4);
    gemm_h(xsh, proh, OUTD, wt + WT_F2, b_f2, out_fpro, NN, OUTD, 2 * OUTD);
}